// round 5
// baseline (speedup 1.0000x reference)
#include <cuda_runtime.h>
#include <cstdint>

// Problem constants (fixed shapes from reference)
#define TT 1024
#define BB 8
#define HH 8
#define NN 32
#define DEPTH 4      // cp.async ring depth (power of 2)
#define ROWP 36      // padded row stride in floats (144B: 16B multiple, conflict-free banks)
#define SLOT (NN * ROWP)            // floats per ring slot
#define SLOTB (SLOT * 4)            // bytes per ring slot

__device__ __forceinline__ void cp16(uint32_t smem_dst, const void* gmem_src) {
    asm volatile("cp.async.cg.shared.global [%0], [%1], 16;\n"
                 :: "r"(smem_dst), "l"(gmem_src) : "memory");
}
__device__ __forceinline__ void cp_commit() {
    asm volatile("cp.async.commit_group;\n" ::: "memory");
}
__device__ __forceinline__ void cp_wait_keep3() {
    asm volatile("cp.async.wait_group %0;\n" :: "n"(DEPTH - 1) : "memory");
}

// Accurate tanh: 2 MUFU (EX2 + RCP) + few ALU; abs error ~1e-7 level.
__device__ __forceinline__ float tanh_acc(float x) {
    float ax = fabsf(x);
    float e  = __expf(-2.0f * ax);
    float r  = __fdividef(1.0f - e, 1.0f + e);
    return copysignf(r, x);
}

__global__ __launch_bounds__(32, 1)
void e86_cell_kernel(const float* __restrict__ x,
                     const float* __restrict__ S0,
                     const float* __restrict__ scale_p,
                     const float* __restrict__ bias_p,
                     float* __restrict__ out,
                     int write_sfinal)
{
    // 16B alignment REQUIRED for cp.async ... 16 destinations.
    __shared__ __align__(16) float buf[DEPTH * SLOT];

    const int head = blockIdx.x;        // head = b*HH + h
    const int lane = threadIdx.x;       // lane = row index i (also column index for v)
    const float scale = scale_p[0];
    const float bias  = bias_p[0];

    // x layout: [T, B, H*N*N]; this head's tile base at t=0.
    // head = b*8 + h and the inner [H*N*N] block is h-major, so offset = head*N*N.
    const float* xh = x + (size_t)head * (NN * NN);
    const size_t xstride = (size_t)BB * HH * NN * NN;   // 65536 floats per step

    // Load S row (lane = row i)
    float S[NN];
    {
        const float* Srow = S0 + (((size_t)head * NN) + lane) * NN;
        #pragma unroll
        for (int j = 0; j < NN; j++) S[j] = Srow[j];
    }

    // Per-lane copy assignment: lane covers rows (lane>>3)+4j, 16B chunk (lane&7).
    const int c8 = lane & 7;
    const int r8 = lane >> 3;
    const uint32_t sb_lane = (uint32_t)__cvta_generic_to_shared(&buf[0])
                           + (uint32_t)(r8 * (ROWP * 4) + c8 * 16);
    const float* gsrc_lane = xh + r8 * NN + c8 * 4;

    // ---- prefetch prologue: fill ring ----
    #pragma unroll
    for (int t = 0; t < DEPTH; t++) {
        const float* src = gsrc_lane + (size_t)t * xstride;
        uint32_t base = sb_lane + (uint32_t)t * SLOTB;
        #pragma unroll
        for (int j = 0; j < 8; j++)
            cp16(base + (uint32_t)(j * 4 * ROWP * 4), src + j * 4 * NN);
        cp_commit();
    }

    // Lane-local read pointers (hoisted out of the loop)
    const float* rowbase = &buf[0] + lane * ROWP;   // row reads (k)
    const float* colbase = &buf[0] + lane;          // column reads (v)

    // ---- main scan ----
    for (int t = 0; t < TT; t++) {
        cp_wait_keep3();
        __syncwarp();

        const int slot = t & (DEPTH - 1);
        const float* rp = rowbase + slot * SLOT;
        const float* cp = colbase + slot * SLOT;

        // k: row mean (lane's own row, 8x LDS.128)
        float ks = 0.0f;
        #pragma unroll
        for (int c = 0; c < 8; c++) {
            float4 q = ((const float4*)rp)[c];
            ks += (q.x + q.y) + (q.z + q.w);
        }
        float k = ks * (1.0f / 32.0f);

        // v: column mean (column = lane), 4 accumulators
        float v0 = 0.f, v1 = 0.f, v2 = 0.f, v3 = 0.f;
        #pragma unroll
        for (int r = 0; r < NN; r += 4) {
            v0 += cp[(r + 0) * ROWP];
            v1 += cp[(r + 1) * ROWP];
            v2 += cp[(r + 2) * ROWP];
            v3 += cp[(r + 3) * ROWP];
        }
        float v = ((v0 + v1) + (v2 + v3)) * (1.0f / 32.0f);

        // done reading this slot -> refill it for t+DEPTH
        __syncwarp();
        if (t + DEPTH < TT) {
            const float* src = gsrc_lane + (size_t)(t + DEPTH) * xstride;
            uint32_t base = sb_lane + (uint32_t)slot * SLOTB;
            #pragma unroll
            for (int j = 0; j < 8; j++)
                cp16(base + (uint32_t)(j * 4 * ROWP * 4), src + j * 4 * NN);
        }
        cp_commit();   // exactly one group per iteration: wait accounting stays exact

        // warp allreduce: sum(k), sum(k^2)
        float s1 = k, s2 = k * k;
        #pragma unroll
        for (int off = 16; off; off >>= 1) {
            s1 += __shfl_xor_sync(0xffffffffu, s1, off);
            s2 += __shfl_xor_sync(0xffffffffu, s2, off);
        }
        float A_mean = s1 * (1.0f / 32.0f);
        float rn  = __fdividef(1.0f, sqrtf(s2) + 1e-6f);
        float knl = k * rn;

        float z    = fmaf(scale, A_mean, bias);
        float beta = __fdividef(1.0f, 1.0f + __expf(-z));

        // gather normalized key into registers
        float kn[NN];
        #pragma unroll
        for (int j = 0; j < NN; j++) kn[j] = __shfl_sync(0xffffffffu, knl, j);

        // retrieved = S[row] . kn
        float r0 = 0.f, r1 = 0.f, r2 = 0.f, r3 = 0.f;
        #pragma unroll
        for (int j = 0; j < NN; j += 4) {
            r0 = fmaf(S[j + 0], kn[j + 0], r0);
            r1 = fmaf(S[j + 1], kn[j + 1], r1);
            r2 = fmaf(S[j + 2], kn[j + 2], r2);
            r3 = fmaf(S[j + 3], kn[j + 3], r3);
        }
        float retr  = (r0 + r1) + (r2 + r3);
        float delta = v - retr;

        // S = tanh(beta*S + delta*kn), and Sq = S_new . kn
        float q0 = 0.f, q1 = 0.f, q2 = 0.f, q3 = 0.f;
        #pragma unroll
        for (int j = 0; j < NN; j += 4) {
            float z0 = fmaf(beta, S[j + 0], delta * kn[j + 0]);
            float z1 = fmaf(beta, S[j + 1], delta * kn[j + 1]);
            float z2 = fmaf(beta, S[j + 2], delta * kn[j + 2]);
            float z3 = fmaf(beta, S[j + 3], delta * kn[j + 3]);
            float n0 = tanh_acc(z0), n1 = tanh_acc(z1);
            float n2 = tanh_acc(z2), n3 = tanh_acc(z3);
            S[j + 0] = n0; S[j + 1] = n1; S[j + 2] = n2; S[j + 3] = n3;
            q0 = fmaf(n0, kn[j + 0], q0);
            q1 = fmaf(n1, kn[j + 1], q1);
            q2 = fmaf(n2, kn[j + 2], q2);
            q3 = fmaf(n3, kn[j + 3], q3);
        }
        float Sq = (q0 + q1) + (q2 + q3);

        // out = Sq * silu(Sq) = Sq^2 * sigmoid(Sq)
        float sg = __fdividef(1.0f, 1.0f + __expf(-Sq));
        float o  = Sq * Sq * sg;

        out[(size_t)t * (BB * HH * NN) + (size_t)head * NN + lane] = o;
    }

    if (write_sfinal) {
        float* dst = out + (size_t)TT * BB * HH * NN + (((size_t)head * NN) + lane) * NN;
        #pragma unroll
        for (int j = 0; j < NN; j++) dst[j] = S[j];
    }
}

extern "C" void kernel_launch(void* const* d_in, const int* in_sizes, int n_in,
                              void* d_out, int out_size)
{
    const float* x       = (const float*)d_in[0];
    const float* S0      = (const float*)d_in[1];
    const float* scale_p = (const float*)d_in[2];
    const float* bias_p  = (const float*)d_in[3];
    float* out = (float*)d_out;

    const int out_main = TT * BB * HH * NN;              // 2,097,152
    const int out_full = out_main + BB * HH * NN * NN;   // 2,162,688
    int write_sfinal = (out_size >= out_full) ? 1 : 0;

    e86_cell_kernel<<<BB * HH, 32>>>(x, S0, scale_p, bias_p, out, write_sfinal);
}

// round 8
// speedup vs baseline: 1.3789x; 1.3789x over previous
#include <cuda_runtime.h>
#include <cstdint>

// Fixed shapes
#define TT 1024
#define BB 8
#define HH 8
#define NN 32
#define DEPTH 4
#define ROWP 36                   // padded row stride (144B): 16B-aligned, conflict-free
#define SLOT (NN * ROWP)
#define SLOTB (SLOT * 4)

__device__ __forceinline__ void cp16(uint32_t d, const void* s) {
    asm volatile("cp.async.cg.shared.global [%0], [%1], 16;\n" :: "r"(d), "l"(s) : "memory");
}
__device__ __forceinline__ void cpcommit() {
    asm volatile("cp.async.commit_group;\n" ::: "memory");
}
template<int N> __device__ __forceinline__ void cpwait() {
    asm volatile("cp.async.wait_group %0;\n" :: "n"(N) : "memory");
}
__device__ __forceinline__ float ex2f(float x) { float y; asm("ex2.approx.f32 %0, %1;" : "=f"(y) : "f"(x)); return y; }
__device__ __forceinline__ float rcpf(float x) { float y; asm("rcp.approx.f32 %0, %1;" : "=f"(y) : "f"(x)); return y; }
__device__ __forceinline__ float sqrtaf(float x){ float y; asm("sqrt.approx.f32 %0, %1;" : "=f"(y) : "f"(x)); return y; }

// tanh(x) = 2/(1+exp(-2x)) - 1, with exp(-2x) = ex2(C2*x).
// Limit-safe for all finite x: e->inf => rcp->0 => -1 ; e->0 => +1.
#define C2  (-2.8853900817779268f)   // -2*log2(e)
#define L2E (1.4426950408889634f)    //  log2(e)

__global__ __launch_bounds__(128, 1)
void e86_cell_kernel(const float* __restrict__ x,
                     const float* __restrict__ S0,
                     const float* __restrict__ scale_p,
                     const float* __restrict__ bias_p,
                     float* __restrict__ out,
                     int write_sfinal)
{
    __shared__ __align__(16) float ring[DEPTH * SLOT];
    __shared__ float kpart[4][NN];   // per-warp row-sum partials (cols 8w..8w+7)
    __shared__ float vpart[4][NN];   // per-warp col-sum partials (rows 8w..8w+7)
    __shared__ float rpart[4][NN];   // retrieved partials
    __shared__ float qpart[4][NN];   // Sq partials

    const int tid  = threadIdx.x;
    const int w    = tid >> 5;       // warp id: owns S columns [8w, 8w+8)
    const int lane = tid & 31;       // row index
    const int head = blockIdx.x;

    const float scale = scale_p[0];
    const float bias  = bias_p[0];
    const float inv32 = 0.03125f;

    const float* xh = x + (size_t)head * (NN * NN);
    const size_t xs = (size_t)(BB * HH * NN * NN);   // 65536 floats per timestep

    // S[lane][8w+j] in registers
    float S[8];
    {
        const float* p = S0 + ((size_t)head * NN + lane) * NN + 8 * w;
        #pragma unroll
        for (int j = 0; j < 8; j++) S[j] = p[j];
    }

    // cp.async plan: 256 16B chunks per 32x32 tile, 2 chunks per thread
    const int c0 = tid, c1 = tid + 128;
    const uint32_t sring = (uint32_t)__cvta_generic_to_shared(ring);
    const uint32_t so0 = (uint32_t)((c0 >> 3) * (ROWP * 4) + (c0 & 7) * 16);
    const uint32_t so1 = (uint32_t)((c1 >> 3) * (ROWP * 4) + (c1 & 7) * 16);
    const float* g0 = xh + (c0 >> 3) * NN + (c0 & 7) * 4;
    const float* g1 = xh + (c1 >> 3) * NN + (c1 & 7) * 4;

    // ---- prologue: fill the 4-slot ring ----
    #pragma unroll
    for (int s = 0; s < DEPTH; s++) {
        cp16(sring + s * SLOTB + so0, g0 + (size_t)s * xs);
        cp16(sring + s * SLOTB + so1, g1 + (size_t)s * xs);
        cpcommit();
    }
    cpwait<3>();            // tile 0 resident
    __syncthreads();

    // P1(0): k/v partials of tile 0
    {
        const float* T = ring;
        const float4* r4 = (const float4*)(T + lane * ROWP + 8 * w);
        float4 a = r4[0], b = r4[1];
        kpart[w][lane] = ((a.x + a.y) + (a.z + a.w)) + ((b.x + b.y) + (b.z + b.w));
        const float* cb = T + (8 * w) * ROWP + lane;
        vpart[w][lane] = ((cb[0] + cb[ROWP]) + (cb[2 * ROWP] + cb[3 * ROWP]))
                       + ((cb[4 * ROWP] + cb[5 * ROWP]) + (cb[6 * ROWP] + cb[7 * ROWP]));
    }

    // ---- main scan: exactly 2 block barriers per step ----
    for (int t = 0; t < TT; t++) {
        const bool hn = (t + 1 < TT);
        if (hn) cpwait<2>();         // tile t+1 resident (group accounting exact)
        __syncthreads();             // BAR_X: ring tiles + P1(t) + qpart(t-1) visible

        // refill slot (t&3) with tile t+4; last read of this slot (P1(t)) was pre-BAR_X
        if (t + 4 < TT) {
            const uint32_t sb = sring + (uint32_t)(t & 3) * SLOTB;
            cp16(sb + so0, g0 + (size_t)(t + 4) * xs);
            cp16(sb + so1, g1 + (size_t)(t + 4) * xs);
        }
        cpcommit();                  // one group per iteration, always

        // P5(t-1): warp 0 finalizes previous step's output
        if (w == 0 && t >= 1) {
            float q = (qpart[0][lane] + qpart[1][lane]) + (qpart[2][lane] + qpart[3][lane]);
            float sg = rcpf(1.0f + ex2f(-q * L2E));
            out[(size_t)(t - 1) * (BB * HH * NN) + (size_t)head * NN + lane] = q * q * sg;
        }

        // P2(t): finish k/v; norm, beta, kn (computed redundantly in each warp)
        float kl = ((kpart[0][lane] + kpart[1][lane]) + (kpart[2][lane] + kpart[3][lane])) * inv32;
        float vl = ((vpart[0][lane] + vpart[1][lane]) + (vpart[2][lane] + vpart[3][lane])) * inv32;
        float s1 = kl, s2 = kl * kl;
        #pragma unroll
        for (int o = 16; o; o >>= 1) {
            s1 += __shfl_xor_sync(0xffffffffu, s1, o);
            s2 += __shfl_xor_sync(0xffffffffu, s2, o);
        }
        const float rn   = rcpf(sqrtaf(s2) + 1e-6f);
        const float beta = rcpf(1.0f + ex2f(fmaf(scale, s1 * inv32, bias) * (-L2E)));
        const float knl  = kl * rn;
        float kn[8];
        #pragma unroll
        for (int j = 0; j < 8; j++) kn[j] = __shfl_sync(0xffffffffu, knl, 8 * w + j);

        // P3(t): retrieved partial over this warp's 8 columns
        {
            float r0 = S[0] * kn[0], r1 = S[1] * kn[1];
            float r2 = S[2] * kn[2], r3 = S[3] * kn[3];
            r0 = fmaf(S[4], kn[4], r0); r1 = fmaf(S[5], kn[5], r1);
            r2 = fmaf(S[6], kn[6], r2); r3 = fmaf(S[7], kn[7], r3);
            rpart[w][lane] = (r0 + r1) + (r2 + r3);
        }
        __syncthreads();             // BAR_Y

        // P4(t): delta; S = tanh(beta*S + delta*kn); Sq partial
        {
            const float ret   = (rpart[0][lane] + rpart[1][lane]) + (rpart[2][lane] + rpart[3][lane]);
            const float delta = vl - ret;
            const float b2 = C2 * beta, d2 = C2 * delta;
            float q0 = 0.f, q1 = 0.f, q2 = 0.f, q3 = 0.f;
            #pragma unroll
            for (int j = 0; j < 8; j += 4) {
                float a0 = fmaf(b2, S[j + 0], d2 * kn[j + 0]);
                float a1 = fmaf(b2, S[j + 1], d2 * kn[j + 1]);
                float a2 = fmaf(b2, S[j + 2], d2 * kn[j + 2]);
                float a3 = fmaf(b2, S[j + 3], d2 * kn[j + 3]);
                float n0 = fmaf(2.0f, rcpf(1.0f + ex2f(a0)), -1.0f);
                float n1 = fmaf(2.0f, rcpf(1.0f + ex2f(a1)), -1.0f);
                float n2 = fmaf(2.0f, rcpf(1.0f + ex2f(a2)), -1.0f);
                float n3 = fmaf(2.0f, rcpf(1.0f + ex2f(a3)), -1.0f);
                S[j + 0] = n0; S[j + 1] = n1; S[j + 2] = n2; S[j + 3] = n3;
                q0 = fmaf(n0, kn[j + 0], q0);
                q1 = fmaf(n1, kn[j + 1], q1);
                q2 = fmaf(n2, kn[j + 2], q2);
                q3 = fmaf(n3, kn[j + 3], q3);
            }
            qpart[w][lane] = (q0 + q1) + (q2 + q3);
        }

        // P1(t+1): k/v partials for next tile (only reads ring; safe post-BAR_Y)
        if (hn) {
            const float* T = ring + ((t + 1) & 3) * SLOT;
            const float4* r4 = (const float4*)(T + lane * ROWP + 8 * w);
            float4 a = r4[0], b = r4[1];
            kpart[w][lane] = ((a.x + a.y) + (a.z + a.w)) + ((b.x + b.y) + (b.z + b.w));
            const float* cb = T + (8 * w) * ROWP + lane;
            vpart[w][lane] = ((cb[0] + cb[ROWP]) + (cb[2 * ROWP] + cb[3 * ROWP]))
                           + ((cb[4 * ROWP] + cb[5 * ROWP]) + (cb[6 * ROWP] + cb[7 * ROWP]));
        }
    }

    // tail: last output + optional S_final
    __syncthreads();
    if (w == 0) {
        float q = (qpart[0][lane] + qpart[1][lane]) + (qpart[2][lane] + qpart[3][lane]);
        float sg = rcpf(1.0f + ex2f(-q * L2E));
        out[(size_t)(TT - 1) * (BB * HH * NN) + (size_t)head * NN + lane] = q * q * sg;
    }
    if (write_sfinal) {
        float* dst = out + (size_t)TT * (BB * HH * NN)
                   + ((size_t)head * NN + lane) * NN + 8 * w;
        #pragma unroll
        for (int j = 0; j < 8; j++) dst[j] = S[j];
    }
}

extern "C" void kernel_launch(void* const* d_in, const int* in_sizes, int n_in,
                              void* d_out, int out_size)
{
    const float* x       = (const float*)d_in[0];
    const float* S0      = (const float*)d_in[1];
    const float* scale_p = (const float*)d_in[2];
    const float* bias_p  = (const float*)d_in[3];
    float* out = (float*)d_out;

    const int out_main = TT * BB * HH * NN;              // 2,097,152
    const int out_full = out_main + BB * HH * NN * NN;   // 2,162,688
    const int write_sfinal = (out_size >= out_full) ? 1 : 0;

    e86_cell_kernel<<<BB * HH, 128>>>(x, S0, scale_p, bias_p, out, write_sfinal);
}

// round 10
// speedup vs baseline: 1.4293x; 1.0365x over previous
#include <cuda_runtime.h>
#include <cstdint>

// Fixed shapes
#define TT 1024
#define BB 8
#define HH 8
#define NN 32
#define DEPTH 4
#define ROWP 36                 // padded row stride (144B): 16B-aligned
#define SLOT (NN * ROWP)
#define SLOTB (SLOT * 4)

__device__ __forceinline__ void cp16(uint32_t d, const void* s) {
    asm volatile("cp.async.cg.shared.global [%0], [%1], 16;\n" :: "r"(d), "l"(s) : "memory");
}
__device__ __forceinline__ void cpcommit() {
    asm volatile("cp.async.commit_group;\n" ::: "memory");
}
template<int N> __device__ __forceinline__ void cpwait() {
    asm volatile("cp.async.wait_group %0;\n" :: "n"(N) : "memory");
}
__device__ __forceinline__ float ex2f(float x) { float y; asm("ex2.approx.f32 %0, %1;" : "=f"(y) : "f"(x)); return y; }
__device__ __forceinline__ float rcpf(float x) { float y; asm("rcp.approx.f32 %0, %1;" : "=f"(y) : "f"(x)); return y; }
__device__ __forceinline__ float sqrtaf(float x){ float y; asm("sqrt.approx.f32 %0, %1;" : "=f"(y) : "f"(x)); return y; }

// tanh(y) = 2/(1+exp(-2y)) - 1 ; exp(-2y) = ex2(C2*y). Limit-safe for all y.
#define C2   (-2.8853900817779268f)   // -2*log2(e)
#define L2E  (1.4426950408889634f)
#define INV32   0.03125f
#define INV1024 0.0009765625f

__global__ __launch_bounds__(128, 1)
void e86_cell_kernel(const float* __restrict__ x,
                     const float* __restrict__ S0,
                     const float* __restrict__ scale_p,
                     const float* __restrict__ bias_p,
                     float* __restrict__ out,
                     int write_sfinal)
{
    __shared__ __align__(16) float ring[DEPTH * SLOT];
    // parity double-buffered exchange arrays [parity][warp][lane]
    __shared__ float rpart[2][4][NN];   // retrieved partials (step t, parity t&1)
    __shared__ float vpart[2][4][NN];   // v partials        (step t, parity t&1)
    __shared__ float qpart[2][4][NN];   // Sq partials       (step t, parity t&1)

    const int tid  = threadIdx.x;
    const int w    = tid >> 5;       // warp owns S COLUMNS [8w, 8w+8)
    const int lane = tid & 31;       // lane = ROW index i
    const int head = blockIdx.x;

    const float scale = scale_p[0];
    const float bias  = bias_p[0];

    const float* xh = x + (size_t)head * (NN * NN);
    const size_t xs = (size_t)(BB * HH * NN * NN);   // 65536 floats per timestep

    // S[j] = S[lane][8w+j]
    float S[8];
    {
        const float* p = S0 + (size_t)head * (NN * NN) + (size_t)lane * NN + 8 * w;
        #pragma unroll
        for (int j = 0; j < 8; j++) S[j] = p[j];
    }

    // cp.async plan: 256 16B chunks/tile, 2 per thread
    const int c0 = tid, c1 = tid + 128;
    const uint32_t sring = (uint32_t)__cvta_generic_to_shared(ring);
    const uint32_t so0 = (uint32_t)((c0 >> 3) * (ROWP * 4) + (c0 & 7) * 16);
    const uint32_t so1 = (uint32_t)((c1 >> 3) * (ROWP * 4) + (c1 & 7) * 16);
    const float* g0 = xh + (c0 >> 3) * NN + (c0 & 7) * 4;
    const float* g1 = xh + (c1 >> 3) * NN + (c1 & 7) * 4;

    // ---- prologue: fill ring with tiles 0..3 ----
    #pragma unroll
    for (int s = 0; s < DEPTH; s++) {
        cp16(sring + s * SLOTB + so0, g0 + (size_t)s * xs);
        cp16(sring + s * SLOTB + so1, g1 + (size_t)s * xs);
        cpcommit();
    }
    cpwait<3>();            // this thread's tile-0 chunks done
    __syncthreads();        // all threads' tile-0 chunks visible

    // Tile-derived state for the CURRENT step (computed one step ahead):
    float kn[8];            // normalized key at this warp's 8 column indices
    float beta;

    // prep(tile in `slot`, parity p): kn, beta (regs) + vpart[p] (smem)
    auto prep = [&](int slot, int p) {
        const float* T = ring + slot * SLOT;
        // rowsum of lane's own row (k[lane]); 8x LDS.128
        const float4* r4 = (const float4*)(T + lane * ROWP);
        float a0 = 0.f, a1 = 0.f, a2 = 0.f, a3 = 0.f;
        #pragma unroll
        for (int c = 0; c < 8; c += 4) {
            float4 q0 = r4[c + 0], q1 = r4[c + 1], q2 = r4[c + 2], q3 = r4[c + 3];
            a0 += (q0.x + q0.y) + (q0.z + q0.w);
            a1 += (q1.x + q1.y) + (q1.z + q1.w);
            a2 += (q2.x + q2.y) + (q2.z + q2.w);
            a3 += (q3.x + q3.y) + (q3.z + q3.w);
        }
        float rowsum = (a0 + a1) + (a2 + a3);
        float klm = rowsum * INV32;                 // k[lane]
        float s1 = rowsum, s2 = klm * klm;
        #pragma unroll
        for (int o = 16; o; o >>= 1) {
            s1 += __shfl_xor_sync(0xffffffffu, s1, o);
            s2 += __shfl_xor_sync(0xffffffffu, s2, o);
        }
        float rn = rcpf(sqrtaf(s2) + 1e-6f);
        beta = rcpf(1.0f + ex2f(-L2E * fmaf(scale, s1 * INV1024, bias)));
        #pragma unroll
        for (int j = 0; j < 8; j++)
            kn[j] = __shfl_sync(0xffffffffu, klm, 8 * w + j) * rn;
        // v partial: rows 8w..8w+7 of column `lane` (conflict-free: consecutive lanes)
        const float* cb = T + (8 * w) * ROWP + lane;
        float vp = ((cb[0] + cb[ROWP]) + (cb[2 * ROWP] + cb[3 * ROWP]))
                 + ((cb[4 * ROWP] + cb[5 * ROWP]) + (cb[6 * ROWP] + cb[7 * ROWP]));
        vpart[p][w][lane] = vp;
    };

    prep(0, 0);   // kn/beta/vpart for step 0

    // ---- main scan: ONE block barrier per step ----
    for (int t = 0; t < TT; t++) {
        const int p  = t & 1;        // parity of step t
        const int pn = p ^ 1;        // parity of step t+1

        // [on-chain] retrieved partial over this warp's 8 columns
        {
            float r0 = S[0] * kn[0], r1 = S[1] * kn[1];
            float r2 = S[2] * kn[2], r3 = S[3] * kn[3];
            r0 = fmaf(S[4], kn[4], r0); r1 = fmaf(S[5], kn[5], r1);
            r2 = fmaf(S[6], kn[6], r2); r3 = fmaf(S[7], kn[7], r3);
            rpart[p][w][lane] = (r0 + r1) + (r2 + r3);
        }

        cpwait<2>();          // this thread's tile t+1 chunks done
        __syncthreads();      // BAR(t): rpart[p], vpart[p], qpart[p^1](t-1), tiles visible

        // refill slot t&3 with tile t+4 (its last reads, prep(t), were pre-BAR)
        if (t + 4 < TT) {
            const uint32_t sb = sring + (uint32_t)(t & 3) * SLOTB;
            cp16(sb + so0, g0 + (size_t)(t + 4) * xs);
            cp16(sb + so1, g1 + (size_t)(t + 4) * xs);
        }
        cpcommit();           // exactly one group per iteration

        // [off-chain] output for step t-1 (warp 0)
        if (w == 0 && t >= 1) {
            float q = (qpart[pn][0][lane] + qpart[pn][1][lane])
                    + (qpart[pn][2][lane] + qpart[pn][3][lane]);
            float sg = rcpf(1.0f + ex2f(-L2E * q));
            out[(size_t)(t - 1) * (BB * HH * NN) + (size_t)head * NN + lane] = q * q * sg;
        }

        // [on-chain] combine: ret, v -> delta; then z, tanh -> S_new
        {
            float ret = (rpart[p][0][lane] + rpart[p][1][lane])
                      + (rpart[p][2][lane] + rpart[p][3][lane]);
            float vv  = ((vpart[p][0][lane] + vpart[p][1][lane])
                      +  (vpart[p][2][lane] + vpart[p][3][lane])) * INV32;
            float delta = vv - ret;
            float b2 = C2 * beta, d2 = C2 * delta;
            #pragma unroll
            for (int j = 0; j < 8; j++) {
                float z = fmaf(b2, S[j], d2 * kn[j]);
                S[j] = fmaf(2.0f, rcpf(1.0f + ex2f(z)), -1.0f);
            }
        }

        // [off-chain] Sq partial for step t (read at t+1 after BAR(t+1))
        {
            float q0 = S[0] * kn[0], q1 = S[1] * kn[1];
            float q2 = S[2] * kn[2], q3 = S[3] * kn[3];
            q0 = fmaf(S[4], kn[4], q0); q1 = fmaf(S[5], kn[5], q1);
            q2 = fmaf(S[6], kn[6], q2); q3 = fmaf(S[7], kn[7], q3);
            qpart[p][w][lane] = (q0 + q1) + (q2 + q3);
        }

        // [off-chain] prep step t+1 from tile t+1 (visible since BAR(t))
        if (t + 1 < TT) prep((t + 1) & 3, pn);
    }

    // tail: output for step TT-1, optional S_final
    __syncthreads();
    {
        const int pl = (TT - 1) & 1;
        if (w == 0) {
            float q = (qpart[pl][0][lane] + qpart[pl][1][lane])
                    + (qpart[pl][2][lane] + qpart[pl][3][lane]);
            float sg = rcpf(1.0f + ex2f(-L2E * q));
            out[(size_t)(TT - 1) * (BB * HH * NN) + (size_t)head * NN + lane] = q * q * sg;
        }
    }
    if (write_sfinal) {
        float* dst = out + (size_t)TT * (BB * HH * NN)
                   + (size_t)head * (NN * NN) + (size_t)lane * NN + 8 * w;
        #pragma unroll
        for (int j = 0; j < 8; j++) dst[j] = S[j];
    }
}

extern "C" void kernel_launch(void* const* d_in, const int* in_sizes, int n_in,
                              void* d_out, int out_size)
{
    const float* x       = (const float*)d_in[0];
    const float* S0      = (const float*)d_in[1];
    const float* scale_p = (const float*)d_in[2];
    const float* bias_p  = (const float*)d_in[3];
    float* out = (float*)d_out;

    const int out_main = TT * BB * HH * NN;              // 2,097,152
    const int out_full = out_main + BB * HH * NN * NN;   // 2,162,688
    const int write_sfinal = (out_size >= out_full) ? 1 : 0;

    e86_cell_kernel<<<BB * HH, 128>>>(x, S0, scale_p, bias_p, out, write_sfinal);
}